// round 3
// baseline (speedup 1.0000x reference)
#include <cuda_runtime.h>
#include <math.h>

// Problem constants
#define T_  32
#define N_  64
#define C_  64
#define L_  64
#define H_  256
#define NA_ 16
#define G3_ 768     // 3*H
#define NCH 2048    // T_*N_ chains per direction

// ---------------------------------------------------------------------------
// Device scratch (static __device__ arrays: allowed; no runtime allocation)
// ---------------------------------------------------------------------------
__device__ float g_XI [2ull * 4096 * 768];          // [dir][m*64+n][3H]  (input projections, bias folded)
__device__ float g_XF1[2048ull * 256];              // MLP hidden 1
__device__ float g_XF2[2048ull * 256];              // MLP hidden 2
__device__ float g_GI [2048ull * 768];              // precomputed cell gi (bias folded)
__device__ float g_GH [2ull * 2048 * 768];          // per-step recurrent gates (no bias)
__device__ float g_H  [2ull * 2048 * 256];          // GRU hidden state per chain
__device__ float g_K  [2048ull * 2 * 64 * 256];     // all GRU outputs: [chain][dir][step][H] (~268 MB)
__device__ float g_h2 [64ull * 256];                // decoder hidden state

// ---------------------------------------------------------------------------
// Zero init for recurrent states
// ---------------------------------------------------------------------------
__global__ void zero_kernel() {
    unsigned i = blockIdx.x * 256u + threadIdx.x;
    if (i < 2u * 2048u * 256u) g_H[i] = 0.f;
    if (i < 64u * 256u)        g_h2[i] = 0.f;
}

// ---------------------------------------------------------------------------
// Generic tiled fp32 GEMM:  C[row][col] = sum_k A[row][k] * B[col][k] (+bias, relu)
//   block tile: 32 rows x 128 cols, K in chunks of 32, 256 threads, 4x4 thread tile
// mode 0: A row = embed[lines[n][m]]   (row = m*64+n)
// mode 1: A row = concat(condition[t][n], aemb[a_prev])   (row = t*64+n, K=320)
// else  : A row = A + row*K
// ---------------------------------------------------------------------------
__global__ __launch_bounds__(256)
void gemm_k(int mode, const float* __restrict__ A, const float* __restrict__ B,
            const float* __restrict__ bias, float* __restrict__ C,
            int cols, int K, int relu,
            const int* __restrict__ lines, const float* __restrict__ embed,
            const float* __restrict__ cond, const float* __restrict__ aemb,
            const int* __restrict__ a_idx)
{
    __shared__ float As[32][36];    // [k][row]  (pad 36 -> float4-aligned rows)
    __shared__ float Bs[32][132];   // [k][col]

    const int row0 = blockIdx.x * 32;
    const int col0 = blockIdx.y * 128;
    const int tid  = threadIdx.x;
    const int tx   = tid & 31;      // col group
    const int ty   = tid >> 5;      // row group

    // A-loader mapping: 32 rows x 32 k, 4 elems/thread
    const int lr  = tid >> 3;        // 0..31 local row
    const int lk4 = (tid & 7) * 4;   // 0..28 local k
    const int grow = row0 + lr;

    const float* Arow = nullptr;
    int ap = 0;
    if (mode == 0) {
        int m = grow >> 6, n = grow & 63;
        Arow = embed + (size_t)lines[n * 64 + m] * H_;
    } else if (mode == 1) {
        int t = grow >> 6;
        ap = (t == 0) ? 0 : a_idx[grow - 64];
    } else {
        Arow = A + (size_t)grow * K;
    }

    // B-loader mapping: 128 cols x 32 k, 16 elems/thread
    const int cc  = tid >> 1;           // 0..127
    const int kk0 = (tid & 1) * 16;     // 0 or 16
    const float* Brow0 = B + (size_t)(col0 + cc) * K;

    float acc[4][4];
#pragma unroll
    for (int i = 0; i < 4; i++)
#pragma unroll
        for (int j = 0; j < 4; j++) acc[i][j] = 0.f;

    for (int k0 = 0; k0 < K; k0 += 32) {
        float4 av;
        if (mode == 1) {
            float t4[4];
#pragma unroll
            for (int i = 0; i < 4; i++) {
                int k = k0 + lk4 + i;
                t4[i] = (k < 64) ? cond[(size_t)grow * 64 + k]
                                 : aemb[(size_t)ap * 256 + (k - 64)];
            }
            av = make_float4(t4[0], t4[1], t4[2], t4[3]);
        } else {
            av = *(const float4*)(Arow + k0 + lk4);
        }
        As[lk4 + 0][lr] = av.x; As[lk4 + 1][lr] = av.y;
        As[lk4 + 2][lr] = av.z; As[lk4 + 3][lr] = av.w;

        const float* bp = Brow0 + k0 + kk0;
#pragma unroll
        for (int i = 0; i < 16; i += 4) {
            float4 bv = *(const float4*)(bp + i);
            Bs[kk0 + i + 0][cc] = bv.x; Bs[kk0 + i + 1][cc] = bv.y;
            Bs[kk0 + i + 2][cc] = bv.z; Bs[kk0 + i + 3][cc] = bv.w;
        }
        __syncthreads();

#pragma unroll
        for (int kk = 0; kk < 32; kk++) {
            float4 a = *(const float4*)&As[kk][ty * 4];
            float4 b = *(const float4*)&Bs[kk][tx * 4];
            acc[0][0] += a.x * b.x; acc[0][1] += a.x * b.y; acc[0][2] += a.x * b.z; acc[0][3] += a.x * b.w;
            acc[1][0] += a.y * b.x; acc[1][1] += a.y * b.y; acc[1][2] += a.y * b.z; acc[1][3] += a.y * b.w;
            acc[2][0] += a.z * b.x; acc[2][1] += a.z * b.y; acc[2][2] += a.z * b.z; acc[2][3] += a.z * b.w;
            acc[3][0] += a.w * b.x; acc[3][1] += a.w * b.y; acc[3][2] += a.w * b.z; acc[3][3] += a.w * b.w;
        }
        __syncthreads();
    }

#pragma unroll
    for (int i = 0; i < 4; i++) {
        int row = row0 + ty * 4 + i;
        float4 v = make_float4(acc[i][0], acc[i][1], acc[i][2], acc[i][3]);
        if (bias) {
            int c = col0 + tx * 4;
            v.x += bias[c]; v.y += bias[c + 1]; v.z += bias[c + 2]; v.w += bias[c + 3];
        }
        if (relu) {
            v.x = fmaxf(v.x, 0.f); v.y = fmaxf(v.y, 0.f);
            v.z = fmaxf(v.z, 0.f); v.w = fmaxf(v.w, 0.f);
        }
        *(float4*)(C + (size_t)row * cols + col0 + tx * 4) = v;
    }
}

// ---------------------------------------------------------------------------
// GRU pointwise update for step j, both directions (2*2048 chains x 256 dims)
// ---------------------------------------------------------------------------
__global__ __launch_bounds__(256)
void gru_update(int j, const int* __restrict__ p_idx,
                const float* __restrict__ bh_f, const float* __restrict__ bh_b)
{
    unsigned idx = blockIdx.x * 256u + threadIdx.x;   // over 2*2048*256 = 2^20
    int hh = idx & 255;
    int c  = (idx >> 8) & 2047;
    int d  = idx >> 19;
    int n  = c & 63;
    int r  = p_idx[c];
    int m  = (d == 0) ? ((j - r + 64) & 63) : ((63 - j - r + 128) & 63);

    const float* xi = g_XI + ((size_t)(d * 4096 + m * 64 + n)) * 768;
    const float* gh = g_GH + ((size_t)(d * 2048 + c)) * 768;
    const float* bh = d ? bh_b : bh_f;

    float h_old = g_H[(size_t)(d * 2048 + c) * 256 + hh];
    float gir = xi[hh],       giz = xi[256 + hh],       gin = xi[512 + hh];
    float ghr = gh[hh] + bh[hh];
    float ghz = gh[256 + hh] + bh[256 + hh];
    float ghn = gh[512 + hh] + bh[512 + hh];

    float rg = 1.f / (1.f + expf(-(gir + ghr)));
    float zg = 1.f / (1.f + expf(-(giz + ghz)));
    float ng = tanhf(gin + rg * ghn);
    float h  = (1.f - zg) * ng + zg * h_old;

    g_H[(size_t)(d * 2048 + c) * 256 + hh] = h;
    g_K[(((size_t)c * 2 + d) * 64 + j) * 256 + hh] = h;
}

// ---------------------------------------------------------------------------
// Block-cooperative matvec: y[o] = W[o][:] . x[:] (+b), 8 lanes per output row
// ---------------------------------------------------------------------------
__device__ __forceinline__ void matvec8(float* __restrict__ y,
                                        const float* __restrict__ W,
                                        const float* __restrict__ b,
                                        const float* __restrict__ x,
                                        int Nout, int K)
{
    int tid  = threadIdx.x;
    int lane = tid & 31, warp = tid >> 5;
    int s = lane & 7, og = lane >> 3;
    for (int ob = warp * 4; ob < Nout; ob += 32) {       // uniform per warp
        int o = ob + og;
        bool valid = (o < Nout);
        const float* w = W + (size_t)(valid ? o : ob) * K;
        float acc = 0.f;
        for (int k = s * 4; k < K; k += 32) {
            float4 wv = *(const float4*)(w + k);
            float4 xv = *(const float4*)(x + k);
            acc += wv.x * xv.x + wv.y * xv.y + wv.z * xv.z + wv.w * xv.w;
        }
        acc += __shfl_down_sync(0xffffffffu, acc, 4);
        acc += __shfl_down_sync(0xffffffffu, acc, 2);
        acc += __shfl_down_sync(0xffffffffu, acc, 1);
        if (s == 0 && valid) y[o] = b ? (acc + b[o]) : acc;
    }
}

// ---------------------------------------------------------------------------
// Decoder step t: GRU cell + pointer/query/critic heads + key attention + actor
// One block per batch element n (64 blocks x 256 threads)
// ---------------------------------------------------------------------------
__global__ __launch_bounds__(256)
void stepC_kernel(int t,
                  const float* __restrict__ cell_wh, const float* __restrict__ cell_bh,
                  const float* __restrict__ pointer_w, const float* __restrict__ pointer_b,
                  const float* __restrict__ query_w, const float* __restrict__ query_b,
                  const float* __restrict__ actor_w, const float* __restrict__ actor_b,
                  const float* __restrict__ critic_w, const float* __restrict__ critic_b,
                  const int* __restrict__ a_idx, const int* __restrict__ p_idx,
                  float* __restrict__ out)
{
    const int n = blockIdx.x;
    const int tid = threadIdx.x;

    __shared__ float sh_h[256];
    __shared__ float sh_gh[768];
    __shared__ float sh_q[256];
    __shared__ float sh_l[128];
    __shared__ float sh_zz[256];
    __shared__ float sh_pl[64];
    __shared__ float sh_al[16];
    __shared__ float sh_v[4];
    __shared__ float s_max, s_sum;

    sh_h[tid] = g_h2[n * 256 + tid];
    __syncthreads();

    // gh = h_prev @ cell_wh^T + cell_bh
    matvec8(sh_gh, cell_wh, cell_bh, sh_h, 768, 256);
    __syncthreads();

    // GRU update
    const float* gi = g_GI + (size_t)(t * 64 + n) * 768;
    float h_old = sh_h[tid];
    float rg = 1.f / (1.f + expf(-(gi[tid]       + sh_gh[tid])));
    float zg = 1.f / (1.f + expf(-(gi[256 + tid] + sh_gh[256 + tid])));
    float ng = tanhf(gi[512 + tid] + rg * sh_gh[512 + tid]);
    float hnew = (1.f - zg) * ng + zg * h_old;
    __syncthreads();
    sh_h[tid] = hnew;
    g_h2[n * 256 + tid] = hnew;
    __syncthreads();

    // heads
    matvec8(sh_pl, pointer_w, pointer_b, sh_h, 64, 256);
    matvec8(sh_q,  query_w,   query_b,   sh_h, 256, 256);
    matvec8(sh_v,  critic_w,  critic_b,  sh_h, 1, 256);
    __syncthreads();

    // softmax over pointer logits (64)
    if (tid < 32) {
        float m = fmaxf(sh_pl[tid], sh_pl[tid + 32]);
#pragma unroll
        for (int o = 16; o > 0; o >>= 1) m = fmaxf(m, __shfl_xor_sync(0xffffffffu, m, o));
        if (tid == 0) s_max = m;
    }
    __syncthreads();
    if (tid < 64) sh_pl[tid] = expf(sh_pl[tid] - s_max);
    __syncthreads();
    if (tid < 32) {
        float s = sh_pl[tid] + sh_pl[tid + 32];
#pragma unroll
        for (int o = 16; o > 0; o >>= 1) s += __shfl_xor_sync(0xffffffffu, s, o);
        if (tid == 0) s_sum = s;
    }

    // attention over this chain's 128 GRU output keys
    const float* Kc = g_K + ((size_t)(t * 64 + n)) * 2 * 64 * 256;  // [128][256]
    __syncthreads();
    matvec8(sh_l, Kc, nullptr, sh_q, 128, 256);
    __syncthreads();

    // zz[u] = sum_k2 l[k2] * Kc[k2][u]
    {
        float acc = 0.f;
#pragma unroll 8
        for (int k2 = 0; k2 < 128; k2++) acc += sh_l[k2] * Kc[(size_t)k2 * 256 + tid];
        sh_zz[tid] = acc;
    }
    __syncthreads();

    // actor logits + softmax (16)
    matvec8(sh_al, actor_w, actor_b, sh_zz, 16, 256);
    __syncthreads();
    if (tid < 32) {
        float v = (tid < 16) ? sh_al[tid] : -1e30f;
        float m = v;
#pragma unroll
        for (int o = 16; o > 0; o >>= 1) m = fmaxf(m, __shfl_xor_sync(0xffffffffu, m, o));
        float e = (tid < 16) ? expf(v - m) : 0.f;
        float s = e;
#pragma unroll
        for (int o = 16; o > 0; o >>= 1) s += __shfl_xor_sync(0xffffffffu, s, o);
        if (tid < 16) sh_al[tid] = e / s;
    }
    __syncthreads();

    // pack output row: [a_t, p_t, v, h(256), a_probs(16), p_probs(64)] = 339
    float* orow = out + ((size_t)(t * 64 + n)) * 339;
    if (tid == 0) {
        orow[0] = (float)a_idx[t * 64 + n];
        orow[1] = (float)p_idx[t * 64 + n];
        orow[2] = sh_v[0];
    }
    orow[3 + tid] = sh_h[tid];
    if (tid < 16) orow[259 + tid] = sh_al[tid];
    if (tid < 64) orow[275 + tid] = sh_pl[tid] / s_sum;
}

// ---------------------------------------------------------------------------
// Launch
// ---------------------------------------------------------------------------
extern "C" void kernel_launch(void* const* d_in, const int* in_sizes, int n_in,
                              void* d_out, int out_size)
{
    const float* condition = (const float*)d_in[0];
    const int*   lines     = (const int*)  d_in[1];
    const int*   a_idx     = (const int*)  d_in[2];
    const int*   p_idx     = (const int*)  d_in[3];
    const float* embed     = (const float*)d_in[4];
    const float* aemb      = (const float*)d_in[5];
    const float* gru_wi_f  = (const float*)d_in[6];
    const float* gru_wh_f  = (const float*)d_in[7];
    const float* gru_bi_f  = (const float*)d_in[8];
    const float* gru_bh_f  = (const float*)d_in[9];
    const float* gru_wi_b  = (const float*)d_in[10];
    const float* gru_wh_b  = (const float*)d_in[11];
    const float* gru_bi_b  = (const float*)d_in[12];
    const float* gru_bh_b  = (const float*)d_in[13];
    const float* f_w1      = (const float*)d_in[14];
    const float* f_b1      = (const float*)d_in[15];
    const float* f_w2      = (const float*)d_in[16];
    const float* f_b2      = (const float*)d_in[17];
    const float* cell_wi   = (const float*)d_in[18];
    const float* cell_wh   = (const float*)d_in[19];
    const float* cell_bi   = (const float*)d_in[20];
    const float* cell_bh   = (const float*)d_in[21];
    const float* critic_w  = (const float*)d_in[22];
    const float* critic_b  = (const float*)d_in[23];
    const float* pointer_w = (const float*)d_in[24];
    const float* pointer_b = (const float*)d_in[25];
    const float* actor_w   = (const float*)d_in[26];
    const float* actor_b   = (const float*)d_in[27];
    const float* query_w   = (const float*)d_in[28];
    const float* query_b   = (const float*)d_in[29];
    float* out = (float*)d_out;

    void *pXI_, *pXF1_, *pXF2_, *pGI_, *pGH_, *pH_;
    cudaGetSymbolAddress(&pXI_,  g_XI);
    cudaGetSymbolAddress(&pXF1_, g_XF1);
    cudaGetSymbolAddress(&pXF2_, g_XF2);
    cudaGetSymbolAddress(&pGI_,  g_GI);
    cudaGetSymbolAddress(&pGH_,  g_GH);
    cudaGetSymbolAddress(&pH_,   g_H);
    float* pXI  = (float*)pXI_;
    float* pXF1 = (float*)pXF1_;
    float* pXF2 = (float*)pXF2_;
    float* pGI  = (float*)pGI_;
    float* pGH  = (float*)pGH_;
    float* pH   = (float*)pH_;

    // 0) zero recurrent states
    zero_kernel<<<4096, 256>>>();

    // 1) input projections XI for both GRU directions: rows = m*64+n (4096)
    gemm_k<<<dim3(128, 6), 256>>>(0, nullptr, gru_wi_f, gru_bi_f, pXI,
                                  768, 256, 0, lines, embed, nullptr, nullptr, nullptr);
    gemm_k<<<dim3(128, 6), 256>>>(0, nullptr, gru_wi_b, gru_bi_b, pXI + 4096ull * 768,
                                  768, 256, 0, lines, embed, nullptr, nullptr, nullptr);

    // 2) decoder MLP + cell input gates, batched over all (t,n)
    gemm_k<<<dim3(64, 2), 256>>>(1, nullptr, f_w1, f_b1, pXF1,
                                 256, 320, 1, nullptr, nullptr, condition, aemb, a_idx);
    gemm_k<<<dim3(64, 2), 256>>>(2, pXF1, f_w2, f_b2, pXF2,
                                 256, 256, 1, nullptr, nullptr, nullptr, nullptr, nullptr);
    gemm_k<<<dim3(64, 6), 256>>>(2, pXF2, cell_wi, cell_bi, pGI,
                                 768, 256, 0, nullptr, nullptr, nullptr, nullptr, nullptr);

    // 3) bidirectional GRU recurrence over 64 timesteps, 2048 chains per dir
    for (int j = 0; j < 64; j++) {
        gemm_k<<<dim3(64, 6), 256>>>(2, pH, gru_wh_f, nullptr, pGH,
                                     768, 256, 0, nullptr, nullptr, nullptr, nullptr, nullptr);
        gemm_k<<<dim3(64, 6), 256>>>(2, pH + 2048ull * 256, gru_wh_b, nullptr, pGH + 2048ull * 768,
                                     768, 256, 0, nullptr, nullptr, nullptr, nullptr, nullptr);
        gru_update<<<4096, 256>>>(j, p_idx, gru_bh_f, gru_bh_b);
    }

    // 4) decoder loop over T=32 steps
    for (int t = 0; t < T_; t++) {
        stepC_kernel<<<64, 256>>>(t, cell_wh, cell_bh, pointer_w, pointer_b,
                                  query_w, query_b, actor_w, actor_b,
                                  critic_w, critic_b, a_idx, p_idx, out);
    }
}

// round 4
// speedup vs baseline: 2.8351x; 2.8351x over previous
#include <cuda_runtime.h>
#include <math.h>
#include <stdint.h>

// Problem constants
#define T_  32
#define N_  64
#define C_  64
#define L_  64
#define H_  256
#define G3_ 768     // 3*H

#define PADH 260    // padded row stride for h in smem (bank-conflict-free A frags)
#define PADG 776    // padded row stride for gates in smem

// ---------------------------------------------------------------------------
// Device scratch
// ---------------------------------------------------------------------------
__device__ float g_XI [2ull * 4096 * 768];          // [dir][m*64+n][3H] input projections (bi folded)
__device__ float g_XF1[2048ull * 256];              // MLP hidden 1
__device__ float g_XF2[2048ull * 256];              // MLP hidden 2
__device__ float g_GI [2048ull * 768];              // cell gi (bias folded)
__device__ float g_K  [2048ull * 2 * 64 * 256];     // all GRU outputs [chain][dir][step][H]
__device__ float g_Bf [2ull * 96 * 32 * 32 * 2];    // Wh permuted into tf32 B-fragment order

// ---------------------------------------------------------------------------
// tf32 helpers
// ---------------------------------------------------------------------------
__device__ __forceinline__ uint32_t f2tf32(float f) {
    uint32_t u;
    asm("cvt.rna.tf32.f32 %0, %1;" : "=r"(u) : "f"(f));
    return u;
}

__device__ __forceinline__ void mma_tf32(float* c, const uint32_t* a, uint32_t b0, uint32_t b1) {
    asm volatile(
        "mma.sync.aligned.m16n8k8.row.col.f32.tf32.tf32.f32 "
        "{%0,%1,%2,%3}, {%4,%5,%6,%7}, {%8,%9}, {%0,%1,%2,%3};"
        : "+f"(c[0]), "+f"(c[1]), "+f"(c[2]), "+f"(c[3])
        : "r"(a[0]), "r"(a[1]), "r"(a[2]), "r"(a[3]), "r"(b0), "r"(b1));
}

// ---------------------------------------------------------------------------
// Permute Wh (both dirs) into B-fragment order, rounded to tf32.
// Layout: g_Bf[d][nt(96)][ks(32)][lane(32)][2]
//   b0 = Wh[n = nt*8 + lane/4][k = ks*8 + lane%4]
//   b1 = Wh[n][k+4]
// ---------------------------------------------------------------------------
__global__ __launch_bounds__(256)
void permute_wh(const float* __restrict__ whf, const float* __restrict__ whb) {
    int idx = blockIdx.x * 256 + threadIdx.x;        // 0 .. 196607
    int lane = idx & 31;
    int ks   = (idx >> 5) & 31;
    int ntd  = idx >> 10;                            // 0..191
    int d    = ntd / 96;
    int nt   = ntd % 96;
    int n = nt * 8 + (lane >> 2);
    int k = ks * 8 + (lane & 3);
    const float* W = d ? whb : whf;
    float v0 = W[n * 256 + k];
    float v1 = W[n * 256 + k + 4];
    g_Bf[(size_t)idx * 2 + 0] = __uint_as_float(f2tf32(v0));
    g_Bf[(size_t)idx * 2 + 1] = __uint_as_float(f2tf32(v1));
}

// ---------------------------------------------------------------------------
// Generic tiled fp32 GEMM (setup phases):
//   C[row][col] = sum_k A[row][k] * B[col][k] (+bias, relu)
// mode 0: A row = embed[lines[n][m]]  (row = m*64+n)
// mode 1: A row = concat(condition[t][n], aemb[a_prev])  (row = t*64+n, K=320)
// else  : A row = A + row*K
// ---------------------------------------------------------------------------
__global__ __launch_bounds__(256)
void gemm_k(int mode, const float* __restrict__ A, const float* __restrict__ B,
            const float* __restrict__ bias, float* __restrict__ C,
            int cols, int K, int relu,
            const int* __restrict__ lines, const float* __restrict__ embed,
            const float* __restrict__ cond, const float* __restrict__ aemb,
            const int* __restrict__ a_idx)
{
    __shared__ float As[32][36];
    __shared__ float Bs[32][132];

    const int row0 = blockIdx.x * 32;
    const int col0 = blockIdx.y * 128;
    const int tid  = threadIdx.x;
    const int tx   = tid & 31;
    const int ty   = tid >> 5;

    const int lr  = tid >> 3;
    const int lk4 = (tid & 7) * 4;
    const int grow = row0 + lr;

    const float* Arow = nullptr;
    int ap = 0;
    if (mode == 0) {
        int m = grow >> 6, n = grow & 63;
        Arow = embed + (size_t)lines[n * 64 + m] * H_;
    } else if (mode == 1) {
        int t = grow >> 6;
        ap = (t == 0) ? 0 : a_idx[grow - 64];
    } else {
        Arow = A + (size_t)grow * K;
    }

    const int cc  = tid >> 1;
    const int kk0 = (tid & 1) * 16;
    const float* Brow0 = B + (size_t)(col0 + cc) * K;

    float acc[4][4];
#pragma unroll
    for (int i = 0; i < 4; i++)
#pragma unroll
        for (int j = 0; j < 4; j++) acc[i][j] = 0.f;

    for (int k0 = 0; k0 < K; k0 += 32) {
        float4 av;
        if (mode == 1) {
            float t4[4];
#pragma unroll
            for (int i = 0; i < 4; i++) {
                int k = k0 + lk4 + i;
                t4[i] = (k < 64) ? cond[(size_t)grow * 64 + k]
                                 : aemb[(size_t)ap * 256 + (k - 64)];
            }
            av = make_float4(t4[0], t4[1], t4[2], t4[3]);
        } else {
            av = *(const float4*)(Arow + k0 + lk4);
        }
        As[lk4 + 0][lr] = av.x; As[lk4 + 1][lr] = av.y;
        As[lk4 + 2][lr] = av.z; As[lk4 + 3][lr] = av.w;

        const float* bp = Brow0 + k0 + kk0;
#pragma unroll
        for (int i = 0; i < 16; i += 4) {
            float4 bv = *(const float4*)(bp + i);
            Bs[kk0 + i + 0][cc] = bv.x; Bs[kk0 + i + 1][cc] = bv.y;
            Bs[kk0 + i + 2][cc] = bv.z; Bs[kk0 + i + 3][cc] = bv.w;
        }
        __syncthreads();

#pragma unroll
        for (int kk = 0; kk < 32; kk++) {
            float4 a = *(const float4*)&As[kk][ty * 4];
            float4 b = *(const float4*)&Bs[kk][tx * 4];
            acc[0][0] += a.x * b.x; acc[0][1] += a.x * b.y; acc[0][2] += a.x * b.z; acc[0][3] += a.x * b.w;
            acc[1][0] += a.y * b.x; acc[1][1] += a.y * b.y; acc[1][2] += a.y * b.z; acc[1][3] += a.y * b.w;
            acc[2][0] += a.z * b.x; acc[2][1] += a.z * b.y; acc[2][2] += a.z * b.z; acc[2][3] += a.z * b.w;
            acc[3][0] += a.w * b.x; acc[3][1] += a.w * b.y; acc[3][2] += a.w * b.z; acc[3][3] += a.w * b.w;
        }
        __syncthreads();
    }

#pragma unroll
    for (int i = 0; i < 4; i++) {
        int row = row0 + ty * 4 + i;
        float4 v = make_float4(acc[i][0], acc[i][1], acc[i][2], acc[i][3]);
        if (bias) {
            int c = col0 + tx * 4;
            v.x += bias[c]; v.y += bias[c + 1]; v.z += bias[c + 2]; v.w += bias[c + 3];
        }
        if (relu) {
            v.x = fmaxf(v.x, 0.f); v.y = fmaxf(v.y, 0.f);
            v.z = fmaxf(v.z, 0.f); v.w = fmaxf(v.w, 0.f);
        }
        *(float4*)(C + (size_t)row * cols + col0 + tx * 4) = v;
    }
}

// ---------------------------------------------------------------------------
// Persistent bidirectional GRU recurrence kernel (tf32 tensor-core).
// 128 blocks x 256 threads. Block owns 32 chains (one direction), loops
// all 64 steps internally. Per step:
//   gates[32,768] = h[32,256] @ Wh^T   (mma.sync m16n8k8 tf32)
//   fused GRU pointwise update; h stays in smem; outputs written to g_K.
// Warp w computes gate columns [w*96, w*96+96) (12 n-tiles of 8).
// ---------------------------------------------------------------------------
__global__ __launch_bounds__(256, 1)
void recur_kernel(const int* __restrict__ p_idx,
                  const float* __restrict__ bh_f, const float* __restrict__ bh_b)
{
    extern __shared__ float sm[];
    float* sh_h  = sm;                          // [32][PADH]
    float* sh_g  = sm + 32 * PADH;              // [32][PADG]
    float* sh_bh = sm + 32 * PADH + 32 * PADG;  // [768]

    const int tid  = threadIdx.x;
    const int lane = tid & 31;
    const int w    = tid >> 5;
    const int gr   = lane >> 2;   // group row
    const int tig  = lane & 3;    // thread-in-group

    const int cg0 = blockIdx.x * 32;     // global chain base (0..4095)
    const int d   = cg0 >> 11;           // direction
    const int c0  = cg0 & 2047;          // chain base within direction

    const float* bh = d ? bh_b : bh_f;
    for (int i = tid; i < 768; i += 256) sh_bh[i] = bh[i];
    for (int i = tid; i < 32 * PADH; i += 256) sh_h[i] = 0.f;

    const float* Bf = g_Bf + (size_t)d * (96 * 32 * 64);

    // update-phase mapping: warp w owns chains [w*4, w*4+4), lane = hh within 32-col blocks
    int   rr[4];
    const float* xib[4];
    float* kout[4];
#pragma unroll
    for (int q = 0; q < 4; q++) {
        int cl = c0 + w * 4 + q;
        rr[q]   = p_idx[cl];
        int n   = cl & 63;
        xib[q]  = g_XI + ((size_t)d * 4096 + (size_t)n) * 768;   // + m*64*768 added per step
        kout[q] = g_K + (((size_t)cl * 2 + d) * 64) * 256;
    }

    __syncthreads();

    for (int j = 0; j < 64; j++) {
        // ---------------- GEMM: gates = h @ Wh^T ----------------
        float acc[12][2][4];
#pragma unroll
        for (int nt = 0; nt < 12; nt++)
#pragma unroll
            for (int mt = 0; mt < 2; mt++)
#pragma unroll
                for (int i = 0; i < 4; i++) acc[nt][mt][i] = 0.f;

        // float2 base pointer for this warp's B fragments at ks=0
        const float2* bp0 = (const float2*)g_Bf +
                            ((size_t)d * (96 * 32 * 32)) + ((size_t)(w * 12) * 32) * 32 + lane;

#pragma unroll 4
        for (int ks = 0; ks < 32; ks++) {
            const int k0 = ks * 8;
            uint32_t a0[4], a1[4];
            a0[0] = f2tf32(sh_h[(gr     ) * PADH + k0 + tig    ]);
            a0[1] = f2tf32(sh_h[(gr +  8) * PADH + k0 + tig    ]);
            a0[2] = f2tf32(sh_h[(gr     ) * PADH + k0 + tig + 4]);
            a0[3] = f2tf32(sh_h[(gr +  8) * PADH + k0 + tig + 4]);
            a1[0] = f2tf32(sh_h[(gr + 16) * PADH + k0 + tig    ]);
            a1[1] = f2tf32(sh_h[(gr + 24) * PADH + k0 + tig    ]);
            a1[2] = f2tf32(sh_h[(gr + 16) * PADH + k0 + tig + 4]);
            a1[3] = f2tf32(sh_h[(gr + 24) * PADH + k0 + tig + 4]);

            const float2* bp = bp0 + (size_t)ks * 32;
#pragma unroll
            for (int nt = 0; nt < 12; nt++) {
                float2 bv = __ldg(bp + (size_t)nt * 1024);   // nt stride = 32*32 float2
                uint32_t b0 = __float_as_uint(bv.x);
                uint32_t b1 = __float_as_uint(bv.y);
                mma_tf32(acc[nt][0], a0, b0, b1);
                mma_tf32(acc[nt][1], a1, b0, b1);
            }
        }

        // stage gates to smem
#pragma unroll
        for (int nt = 0; nt < 12; nt++) {
            int col = w * 96 + nt * 8 + 2 * tig;
#pragma unroll
            for (int mt = 0; mt < 2; mt++) {
                int row = mt * 16 + gr;
                *(float2*)&sh_g[(row    ) * PADG + col] = make_float2(acc[nt][mt][0], acc[nt][mt][1]);
                *(float2*)&sh_g[(row + 8) * PADG + col] = make_float2(acc[nt][mt][2], acc[nt][mt][3]);
            }
        }
        __syncthreads();

        // ---------------- fused GRU update ----------------
        int m4[4];
#pragma unroll
        for (int q = 0; q < 4; q++)
            m4[q] = (d == 0) ? ((j - rr[q] + 64) & 63) : ((63 - j - rr[q] + 128) & 63);

#pragma unroll 4
        for (int u = 0; u < 32; u++) {
            const int q  = u & 3;
            const int uc = w * 4 + q;
            const int hh = (u >> 2) * 32 + lane;
            const float* xi = xib[q] + (size_t)m4[q] * 64 * 768;

            float xr = __ldg(xi + hh);
            float xz = __ldg(xi + 256 + hh);
            float xn = __ldg(xi + 512 + hh);
            float ghr = sh_g[uc * PADG + hh]       + sh_bh[hh];
            float ghz = sh_g[uc * PADG + 256 + hh] + sh_bh[256 + hh];
            float ghn = sh_g[uc * PADG + 512 + hh] + sh_bh[512 + hh];

            float rg = __fdividef(1.f, 1.f + __expf(-(xr + ghr)));
            float zg = __fdividef(1.f, 1.f + __expf(-(xz + ghz)));
            float tn;
            asm("tanh.approx.f32 %0, %1;" : "=f"(tn) : "f"(xn + rg * ghn));

            float h = sh_h[uc * PADH + hh];
            h = (1.f - zg) * tn + zg * h;
            sh_h[uc * PADH + hh] = h;
            kout[q][(size_t)j * 256 + hh] = h;
        }
        __syncthreads();
    }
}

// ---------------------------------------------------------------------------
// Block-cooperative matvec (decoder): y[o] = W[o][:] . x[:] (+b)
// ---------------------------------------------------------------------------
__device__ __forceinline__ void matvec8(float* __restrict__ y,
                                        const float* __restrict__ W,
                                        const float* __restrict__ b,
                                        const float* __restrict__ x,
                                        int Nout, int K)
{
    int tid  = threadIdx.x;
    int lane = tid & 31, warp = tid >> 5;
    int s = lane & 7, og = lane >> 3;
    for (int ob = warp * 4; ob < Nout; ob += 32) {
        int o = ob + og;
        bool valid = (o < Nout);
        const float* w = W + (size_t)(valid ? o : ob) * K;
        float acc = 0.f;
        for (int k = s * 4; k < K; k += 32) {
            float4 wv = *(const float4*)(w + k);
            float4 xv = *(const float4*)(x + k);
            acc += wv.x * xv.x + wv.y * xv.y + wv.z * xv.z + wv.w * xv.w;
        }
        acc += __shfl_down_sync(0xffffffffu, acc, 4);
        acc += __shfl_down_sync(0xffffffffu, acc, 2);
        acc += __shfl_down_sync(0xffffffffu, acc, 1);
        if (s == 0 && valid) y[o] = b ? (acc + b[o]) : acc;
    }
}

// ---------------------------------------------------------------------------
// Persistent decoder: one block per batch element n, loops all T=32 steps.
// ---------------------------------------------------------------------------
__global__ __launch_bounds__(256)
void decoder_kernel(const float* __restrict__ cell_wh, const float* __restrict__ cell_bh,
                    const float* __restrict__ pointer_w, const float* __restrict__ pointer_b,
                    const float* __restrict__ query_w, const float* __restrict__ query_b,
                    const float* __restrict__ actor_w, const float* __restrict__ actor_b,
                    const float* __restrict__ critic_w, const float* __restrict__ critic_b,
                    const int* __restrict__ a_idx, const int* __restrict__ p_idx,
                    float* __restrict__ out)
{
    const int n = blockIdx.x;
    const int tid = threadIdx.x;

    __shared__ float sh_h[256];
    __shared__ float sh_gh[768];
    __shared__ float sh_q[256];
    __shared__ float sh_l[128];
    __shared__ float sh_zz[256];
    __shared__ float sh_pl[64];
    __shared__ float sh_al[16];
    __shared__ float sh_v[4];
    __shared__ float s_max, s_sum;

    sh_h[tid] = 0.f;
    __syncthreads();

    for (int t = 0; t < T_; t++) {
        __syncthreads();
        matvec8(sh_gh, cell_wh, cell_bh, sh_h, 768, 256);
        __syncthreads();

        const float* gi = g_GI + (size_t)(t * 64 + n) * 768;
        float h_old = sh_h[tid];
        float rg = 1.f / (1.f + __expf(-(gi[tid]       + sh_gh[tid])));
        float zg = 1.f / (1.f + __expf(-(gi[256 + tid] + sh_gh[256 + tid])));
        float tn;
        asm("tanh.approx.f32 %0, %1;" : "=f"(tn) : "f"(gi[512 + tid] + rg * sh_gh[512 + tid]));
        float hnew = (1.f - zg) * tn + zg * h_old;
        __syncthreads();
        sh_h[tid] = hnew;
        __syncthreads();

        matvec8(sh_pl, pointer_w, pointer_b, sh_h, 64, 256);
        matvec8(sh_q,  query_w,   query_b,   sh_h, 256, 256);
        matvec8(sh_v,  critic_w,  critic_b,  sh_h, 1, 256);
        __syncthreads();

        if (tid < 32) {
            float m = fmaxf(sh_pl[tid], sh_pl[tid + 32]);
#pragma unroll
            for (int o = 16; o > 0; o >>= 1) m = fmaxf(m, __shfl_xor_sync(0xffffffffu, m, o));
            if (tid == 0) s_max = m;
        }
        __syncthreads();
        if (tid < 64) sh_pl[tid] = __expf(sh_pl[tid] - s_max);
        __syncthreads();
        if (tid < 32) {
            float s = sh_pl[tid] + sh_pl[tid + 32];
#pragma unroll
            for (int o = 16; o > 0; o >>= 1) s += __shfl_xor_sync(0xffffffffu, s, o);
            if (tid == 0) s_sum = s;
        }

        const float* Kc = g_K + ((size_t)(t * 64 + n)) * 2 * 64 * 256;   // [128][256]
        __syncthreads();
        matvec8(sh_l, Kc, nullptr, sh_q, 128, 256);
        __syncthreads();

        {
            float acc = 0.f;
#pragma unroll 8
            for (int k2 = 0; k2 < 128; k2++) acc += sh_l[k2] * Kc[(size_t)k2 * 256 + tid];
            sh_zz[tid] = acc;
        }
        __syncthreads();

        matvec8(sh_al, actor_w, actor_b, sh_zz, 16, 256);
        __syncthreads();
        if (tid < 32) {
            float v = (tid < 16) ? sh_al[tid] : -1e30f;
            float m = v;
#pragma unroll
            for (int o = 16; o > 0; o >>= 1) m = fmaxf(m, __shfl_xor_sync(0xffffffffu, m, o));
            float e = (tid < 16) ? __expf(v - m) : 0.f;
            float s = e;
#pragma unroll
            for (int o = 16; o > 0; o >>= 1) s += __shfl_xor_sync(0xffffffffu, s, o);
            if (tid < 16) sh_al[tid] = e / s;
        }
        __syncthreads();

        float* orow = out + ((size_t)(t * 64 + n)) * 339;
        if (tid == 0) {
            orow[0] = (float)a_idx[t * 64 + n];
            orow[1] = (float)p_idx[t * 64 + n];
            orow[2] = sh_v[0];
        }
        orow[3 + tid] = sh_h[tid];
        if (tid < 16) orow[259 + tid] = sh_al[tid];
        if (tid < 64) orow[275 + tid] = sh_pl[tid] / s_sum;
    }
}

// ---------------------------------------------------------------------------
// Launch
// ---------------------------------------------------------------------------
extern "C" void kernel_launch(void* const* d_in, const int* in_sizes, int n_in,
                              void* d_out, int out_size)
{
    const float* condition = (const float*)d_in[0];
    const int*   lines     = (const int*)  d_in[1];
    const int*   a_idx     = (const int*)  d_in[2];
    const int*   p_idx     = (const int*)  d_in[3];
    const float* embed     = (const float*)d_in[4];
    const float* aemb      = (const float*)d_in[5];
    const float* gru_wi_f  = (const float*)d_in[6];
    const float* gru_wh_f  = (const float*)d_in[7];
    const float* gru_bi_f  = (const float*)d_in[8];
    const float* gru_bh_f  = (const float*)d_in[9];
    const float* gru_wi_b  = (const float*)d_in[10];
    const float* gru_wh_b  = (const float*)d_in[11];
    const float* gru_bi_b  = (const float*)d_in[12];
    const float* gru_bh_b  = (const float*)d_in[13];
    const float* f_w1      = (const float*)d_in[14];
    const float* f_b1      = (const float*)d_in[15];
    const float* f_w2      = (const float*)d_in[16];
    const float* f_b2      = (const float*)d_in[17];
    const float* cell_wi   = (const float*)d_in[18];
    const float* cell_wh   = (const float*)d_in[19];
    const float* cell_bi   = (const float*)d_in[20];
    const float* cell_bh   = (const float*)d_in[21];
    const float* critic_w  = (const float*)d_in[22];
    const float* critic_b  = (const float*)d_in[23];
    const float* pointer_w = (const float*)d_in[24];
    const float* pointer_b = (const float*)d_in[25];
    const float* actor_w   = (const float*)d_in[26];
    const float* actor_b   = (const float*)d_in[27];
    const float* query_w   = (const float*)d_in[28];
    const float* query_b   = (const float*)d_in[29];
    float* out = (float*)d_out;

    void *pXI_, *pXF1_, *pXF2_, *pGI_;
    cudaGetSymbolAddress(&pXI_,  g_XI);
    cudaGetSymbolAddress(&pXF1_, g_XF1);
    cudaGetSymbolAddress(&pXF2_, g_XF2);
    cudaGetSymbolAddress(&pGI_,  g_GI);
    float* pXI  = (float*)pXI_;
    float* pXF1 = (float*)pXF1_;
    float* pXF2 = (float*)pXF2_;
    float* pGI  = (float*)pGI_;

    // recurrence kernel dynamic smem
    const int SMEM_REC = (32 * PADH + 32 * PADG + 768) * 4;
    static int attr_set = 0;
    cudaFuncSetAttribute(recur_kernel, cudaFuncAttributeMaxDynamicSharedMemorySize, SMEM_REC);
    (void)attr_set;

    // 0) permute/round recurrent weights into tf32 fragment order
    permute_wh<<<768, 256>>>(gru_wh_f, gru_wh_b);

    // 1) input projections XI for both GRU directions: rows = m*64+n (4096)
    gemm_k<<<dim3(128, 6), 256>>>(0, nullptr, gru_wi_f, gru_bi_f, pXI,
                                  768, 256, 0, lines, embed, nullptr, nullptr, nullptr);
    gemm_k<<<dim3(128, 6), 256>>>(0, nullptr, gru_wi_b, gru_bi_b, pXI + 4096ull * 768,
                                  768, 256, 0, lines, embed, nullptr, nullptr, nullptr);

    // 2) decoder MLP + cell input gates, batched over all (t,n)
    gemm_k<<<dim3(64, 2), 256>>>(1, nullptr, f_w1, f_b1, pXF1,
                                 256, 320, 1, nullptr, nullptr, condition, aemb, a_idx);
    gemm_k<<<dim3(64, 2), 256>>>(2, pXF1, f_w2, f_b2, pXF2,
                                 256, 256, 1, nullptr, nullptr, nullptr, nullptr, nullptr);
    gemm_k<<<dim3(64, 6), 256>>>(2, pXF2, cell_wi, cell_bi, pGI,
                                 768, 256, 0, nullptr, nullptr, nullptr, nullptr, nullptr);

    // 3) persistent bidirectional GRU recurrence (tensor cores, tf32)
    recur_kernel<<<128, 256, SMEM_REC>>>(p_idx, gru_bh_f, gru_bh_b);

    // 4) persistent decoder over T=32 steps
    decoder_kernel<<<64, 256>>>(cell_wh, cell_bh, pointer_w, pointer_b,
                                query_w, query_b, actor_w, actor_b,
                                critic_w, critic_b, a_idx, p_idx, out);
}

// round 6
// speedup vs baseline: 3.5354x; 1.2470x over previous
#include <cuda_runtime.h>
#include <cuda_fp16.h>
#include <math.h>
#include <stdint.h>

// Problem constants
#define T_  32
#define N_  64
#define H_  256

#define STRH 264    // h16 smem row stride (halfs)
#define STRX 772    // sXI smem row stride (floats)

// ---------------------------------------------------------------------------
// Device scratch
// ---------------------------------------------------------------------------
__device__ float  g_XI [2ull * 4096 * 768];         // [dir][m*64+n][3H] fp32
__device__ float  g_XF1[2048ull * 256];
__device__ float  g_XF2[2048ull * 256];
__device__ float  g_GI [2048ull * 768];             // cell gi fp32
__device__ float  g_K  [2048ull * 2 * 64 * 256];    // GRU outputs fp32 [chain][dir][step][H]
__device__ uint4  g_Bh4[2ull * 96 * 8 * 32];        // Wh fp16 B-fragments [d][nt][kc2][lane]

// ---------------------------------------------------------------------------
// helpers
// ---------------------------------------------------------------------------
__device__ __forceinline__ uint32_t packh2(float a, float b) {
    __half2 h = __floats2half2_rn(a, b);
    return *(uint32_t*)&h;
}

__device__ __forceinline__ void mma_f16(float* c, uint32_t a0, uint32_t a1, uint32_t a2,
                                        uint32_t a3, uint32_t b0, uint32_t b1) {
    asm volatile(
        "mma.sync.aligned.m16n8k16.row.col.f32.f16.f16.f32 "
        "{%0,%1,%2,%3}, {%4,%5,%6,%7}, {%8,%9}, {%0,%1,%2,%3};"
        : "+f"(c[0]), "+f"(c[1]), "+f"(c[2]), "+f"(c[3])
        : "r"(a0), "r"(a1), "r"(a2), "r"(a3), "r"(b0), "r"(b1));
}

__device__ __forceinline__ uint32_t smem_u32(const void* p) {
    return (uint32_t)__cvta_generic_to_shared(p);
}

// ---------------------------------------------------------------------------
// Permute Wh (both dirs) into fp16 B-fragment order for mma.m16n8k16.
// g_Bh4[((d*96+nt)*8+kc2)*32 + lane]:
//   n = nt*8 + (lane>>2), k = kc2*32 + 2*(lane&3)
//   .x = W[n][k+0,1]  .y = W[n][k+8,9]  .z = W[n][k+16,17]  .w = W[n][k+24,25]
// ---------------------------------------------------------------------------
__global__ __launch_bounds__(256)
void permute_wh16(const float* __restrict__ whf, const float* __restrict__ whb) {
    int idx = blockIdx.x * 256 + threadIdx.x;
    if (idx >= 2 * 96 * 8 * 32) return;
    int lane = idx & 31;
    int kc2  = (idx >> 5) & 7;
    int nt_v = idx >> 8;
    int d    = nt_v / 96;
    int nt   = nt_v % 96;
    int gr = lane >> 2, tig = lane & 3;
    const float* W = d ? whb : whf;
    const float* wr = W + (size_t)(nt * 8 + gr) * 256 + kc2 * 32 + 2 * tig;
    uint4 o;
    o.x = packh2(wr[0],  wr[1]);
    o.y = packh2(wr[8],  wr[9]);
    o.z = packh2(wr[16], wr[17]);
    o.w = packh2(wr[24], wr[25]);
    g_Bh4[idx] = o;
}

// ---------------------------------------------------------------------------
// Generic tiled fp32 GEMM (setup): C[row][col] = sum_k A[row][k]*B[col][k] (+bias, relu)
// mode 0: A row = embed[lines[n][m]] (row = m*64+n)
// mode 1: A row = concat(condition[t][n], aemb[a_prev]) (row = t*64+n, K=320)
// else  : A row = A + row*K
// ---------------------------------------------------------------------------
__global__ __launch_bounds__(256)
void gemm_k(int mode, const float* __restrict__ A, const float* __restrict__ B,
            const float* __restrict__ bias, float* __restrict__ C,
            int cols, int K, int relu,
            const int* __restrict__ lines, const float* __restrict__ embed,
            const float* __restrict__ cond, const float* __restrict__ aemb,
            const int* __restrict__ a_idx)
{
    __shared__ float As[32][36];
    __shared__ float Bs[32][132];

    const int row0 = blockIdx.x * 32;
    const int col0 = blockIdx.y * 128;
    const int tid  = threadIdx.x;
    const int tx   = tid & 31;
    const int ty   = tid >> 5;

    const int lr  = tid >> 3;
    const int lk4 = (tid & 7) * 4;
    const int grow = row0 + lr;

    const float* Arow = nullptr;
    int ap = 0;
    if (mode == 0) {
        int m = grow >> 6, n = grow & 63;
        Arow = embed + (size_t)lines[n * 64 + m] * H_;
    } else if (mode == 1) {
        int t = grow >> 6;
        ap = (t == 0) ? 0 : a_idx[grow - 64];
    } else {
        Arow = A + (size_t)grow * K;
    }

    const int cc  = tid >> 1;
    const int kk0 = (tid & 1) * 16;
    const float* Brow0 = B + (size_t)(col0 + cc) * K;

    float acc[4][4];
#pragma unroll
    for (int i = 0; i < 4; i++)
#pragma unroll
        for (int j = 0; j < 4; j++) acc[i][j] = 0.f;

    for (int k0 = 0; k0 < K; k0 += 32) {
        float4 av;
        if (mode == 1) {
            float t4[4];
#pragma unroll
            for (int i = 0; i < 4; i++) {
                int k = k0 + lk4 + i;
                t4[i] = (k < 64) ? cond[(size_t)grow * 64 + k]
                                 : aemb[(size_t)ap * 256 + (k - 64)];
            }
            av = make_float4(t4[0], t4[1], t4[2], t4[3]);
        } else {
            av = *(const float4*)(Arow + k0 + lk4);
        }
        As[lk4 + 0][lr] = av.x; As[lk4 + 1][lr] = av.y;
        As[lk4 + 2][lr] = av.z; As[lk4 + 3][lr] = av.w;

        const float* bp = Brow0 + k0 + kk0;
#pragma unroll
        for (int i = 0; i < 16; i += 4) {
            float4 bv = *(const float4*)(bp + i);
            Bs[kk0 + i + 0][cc] = bv.x; Bs[kk0 + i + 1][cc] = bv.y;
            Bs[kk0 + i + 2][cc] = bv.z; Bs[kk0 + i + 3][cc] = bv.w;
        }
        __syncthreads();

#pragma unroll
        for (int kk = 0; kk < 32; kk++) {
            float4 a = *(const float4*)&As[kk][ty * 4];
            float4 b = *(const float4*)&Bs[kk][tx * 4];
            acc[0][0] += a.x * b.x; acc[0][1] += a.x * b.y; acc[0][2] += a.x * b.z; acc[0][3] += a.x * b.w;
            acc[1][0] += a.y * b.x; acc[1][1] += a.y * b.y; acc[1][2] += a.y * b.z; acc[1][3] += a.y * b.w;
            acc[2][0] += a.z * b.x; acc[2][1] += a.z * b.y; acc[2][2] += a.z * b.z; acc[2][3] += a.z * b.w;
            acc[3][0] += a.w * b.x; acc[3][1] += a.w * b.y; acc[3][2] += a.w * b.z; acc[3][3] += a.w * b.w;
        }
        __syncthreads();
    }

#pragma unroll
    for (int i = 0; i < 4; i++) {
        int row = row0 + ty * 4 + i;
        float4 v = make_float4(acc[i][0], acc[i][1], acc[i][2], acc[i][3]);
        if (bias) {
            int c = col0 + tx * 4;
            v.x += bias[c]; v.y += bias[c + 1]; v.z += bias[c + 2]; v.w += bias[c + 3];
        }
        if (relu) {
            v.x = fmaxf(v.x, 0.f); v.y = fmaxf(v.y, 0.f);
            v.z = fmaxf(v.z, 0.f); v.w = fmaxf(v.w, 0.f);
        }
        *(float4*)(C + (size_t)row * cols + col0 + tx * 4) = v;
    }
}

// ---------------------------------------------------------------------------
// Persistent bidirectional GRU recurrence (fp16 MMA, fp32 state).
// 128 blocks (= 2 dirs x 64) x 512 threads. Block owns 32 chains; 64 steps.
// Warp = (mh in {0,1}: 16 rows) x (w8 in 0..7: 32 cols per gate -> FULL 256).
// Per step: gates[32,768] = h16[32,256] @ Wh^T; XI staged via cp.async;
// GRU update in registers (hold = fp32 h state); h written fp16 to smem
// (next step's MMA A input) and fp32 to g_K.
// ---------------------------------------------------------------------------
__global__ __launch_bounds__(512, 1)
void recur_kernel(const int* __restrict__ p_idx,
                  const float* __restrict__ bh_f, const float* __restrict__ bh_b)
{
    extern __shared__ char smraw[];
    __half* h16 = (__half*)smraw;                            // 32*STRH halfs = 16896 B
    float*  sbh = (float*)(smraw + 32 * STRH * 2);           // 768 floats
    float*  sXI = sbh + 768;                                 // 32*STRX floats = 98816 B
    int*    rrs = (int*)(sXI + 32 * STRX);                   // 32 ints

    const int tid  = threadIdx.x;
    const int lane = tid & 31;
    const int w    = tid >> 5;        // 0..15
    const int w8   = w & 7;
    const int mh   = w >> 3;
    const int gr   = lane >> 2;
    const int tig  = lane & 3;

    const int d  = blockIdx.x >> 6;            // direction
    const int c0 = (blockIdx.x & 63) * 32;     // chain base within direction

    const float* bh = d ? bh_b : bh_f;
    for (int i = tid; i < 768; i += 512) sbh[i] = bh[i];
    for (int i = tid; i < 32 * STRH / 2; i += 512) ((uint32_t*)h16)[i] = 0u;
    if (tid < 32) rrs[tid] = p_idx[c0 + tid];

    // ldmatrix base: row = mh*16 + (lane&15), col halfs = (lane>>4)*8
    const uint32_t abase = smem_u32(h16) + (uint32_t)((mh * 16 + (lane & 15)) * STRH * 2
                                                      + (lane >> 4) * 16);

    const uint4* bb = g_Bh4 + (size_t)d * (96 * 8 * 32);

    float hold[2][4][2];
#pragma unroll
    for (int a = 0; a < 2; a++)
#pragma unroll
        for (int b = 0; b < 4; b++) { hold[a][b][0] = 0.f; hold[a][b][1] = 0.f; }

    __syncthreads();

    for (int j = 0; j < 64; j++) {
        // ---- stage this step's XI rows into smem via cp.async (warp w: rows 2w, 2w+1)
        {
#pragma unroll
            for (int rw = 0; rw < 2; rw++) {
                int row = w * 2 + rw;
                int rr  = rrs[row];
                int m   = (d == 0) ? ((j - rr + 64) & 63) : ((63 - j - rr + 128) & 63);
                int n   = (c0 + row) & 63;
                const float* src = g_XI + ((size_t)d * 4096 + m * 64 + n) * 768 + lane * 4;
                uint32_t dst = smem_u32(sXI + row * STRX + lane * 4);
#pragma unroll
                for (int it = 0; it < 6; it++) {
                    asm volatile("cp.async.cg.shared.global [%0], [%1], 16;"
                                 :: "r"(dst + it * 512), "l"(src + it * 128));
                }
            }
            asm volatile("cp.async.commit_group;");
        }

        // ---- MMA: gates = h @ Wh^T
        float acc[3][4][4];
#pragma unroll
        for (int g = 0; g < 3; g++)
#pragma unroll
            for (int nt = 0; nt < 4; nt++)
#pragma unroll
                for (int i = 0; i < 4; i++) acc[g][nt][i] = 0.f;

#pragma unroll
        for (int kc2 = 0; kc2 < 8; kc2++) {
            uint32_t a0[4], a1[4];
            {
                uint32_t addr = abase + (uint32_t)(kc2 * 64);
                asm volatile("ldmatrix.sync.aligned.m8n8.x4.shared.b16 {%0,%1,%2,%3}, [%4];"
                             : "=r"(a0[0]), "=r"(a0[1]), "=r"(a0[2]), "=r"(a0[3]) : "r"(addr));
                asm volatile("ldmatrix.sync.aligned.m8n8.x4.shared.b16 {%0,%1,%2,%3}, [%4];"
                             : "=r"(a1[0]), "=r"(a1[1]), "=r"(a1[2]), "=r"(a1[3]) : "r"(addr + 32));
            }
#pragma unroll
            for (int g = 0; g < 3; g++) {
                uint4 bv[4];
#pragma unroll
                for (int nt = 0; nt < 4; nt++)
                    bv[nt] = __ldg(bb + ((size_t)((g * 32 + w8 * 4 + nt) * 8 + kc2)) * 32 + lane);
#pragma unroll
                for (int nt = 0; nt < 4; nt++) {
                    mma_f16(acc[g][nt], a0[0], a0[1], a0[2], a0[3], bv[nt].x, bv[nt].y);
                    mma_f16(acc[g][nt], a1[0], a1[1], a1[2], a1[3], bv[nt].z, bv[nt].w);
                }
            }
        }

        asm volatile("cp.async.wait_group 0;" ::: "memory");
        __syncthreads();   // all ldmatrix reads done; XI staged

        // ---- fused GRU update (in registers)
#pragma unroll
        for (int nt = 0; nt < 4; nt++) {
            const int colb = w8 * 32 + nt * 8 + 2 * tig;
#pragma unroll
            for (int rw = 0; rw < 2; rw++) {
                const int row = mh * 16 + gr + rw * 8;
                const float* xr = &sXI[row * STRX + colb];
                float2 xir = *(const float2*)(xr);
                float2 xiz = *(const float2*)(xr + 256);
                float2 xin = *(const float2*)(xr + 512);

                float ghr0 = acc[0][nt][rw * 2 + 0] + sbh[colb];
                float ghr1 = acc[0][nt][rw * 2 + 1] + sbh[colb + 1];
                float ghz0 = acc[1][nt][rw * 2 + 0] + sbh[256 + colb];
                float ghz1 = acc[1][nt][rw * 2 + 1] + sbh[256 + colb + 1];
                float ghn0 = acc[2][nt][rw * 2 + 0] + sbh[512 + colb];
                float ghn1 = acc[2][nt][rw * 2 + 1] + sbh[512 + colb + 1];

                float r0 = __fdividef(1.f, 1.f + __expf(-(xir.x + ghr0)));
                float r1 = __fdividef(1.f, 1.f + __expf(-(xir.y + ghr1)));
                float z0 = __fdividef(1.f, 1.f + __expf(-(xiz.x + ghz0)));
                float z1 = __fdividef(1.f, 1.f + __expf(-(xiz.y + ghz1)));
                float n0, n1;
                asm("tanh.approx.f32 %0, %1;" : "=f"(n0) : "f"(xin.x + r0 * ghn0));
                asm("tanh.approx.f32 %0, %1;" : "=f"(n1) : "f"(xin.y + r1 * ghn1));

                float h0 = (1.f - z0) * n0 + z0 * hold[rw][nt][0];
                float h1 = (1.f - z1) * n1 + z1 * hold[rw][nt][1];
                hold[rw][nt][0] = h0;
                hold[rw][nt][1] = h1;

                *(__half2*)&h16[row * STRH + colb] = __floats2half2_rn(h0, h1);
                *(float2*)(g_K + ((((size_t)(c0 + row)) * 2 + d) * 64 + j) * 256 + colb)
                    = make_float2(h0, h1);
            }
        }
        __syncthreads();   // h16 updated before next step's ldmatrix
    }
}

// ---------------------------------------------------------------------------
// Block-cooperative matvec (decoder, fp32): y[o] = W[o][:] . x[:] (+b)
// ---------------------------------------------------------------------------
__device__ __forceinline__ void matvec8(float* __restrict__ y,
                                        const float* __restrict__ W,
                                        const float* __restrict__ b,
                                        const float* __restrict__ x,
                                        int Nout, int K)
{
    int tid  = threadIdx.x;
    int lane = tid & 31, warp = tid >> 5;
    int s = lane & 7, og = lane >> 3;
    for (int ob = warp * 4; ob < Nout; ob += 32) {
        int o = ob + og;
        bool valid = (o < Nout);
        const float* w = W + (size_t)(valid ? o : ob) * K;
        float acc = 0.f;
        for (int k = s * 4; k < K; k += 32) {
            float4 wv = *(const float4*)(w + k);
            float4 xv = *(const float4*)(x + k);
            acc += wv.x * xv.x + wv.y * xv.y + wv.z * xv.z + wv.w * xv.w;
        }
        acc += __shfl_down_sync(0xffffffffu, acc, 4);
        acc += __shfl_down_sync(0xffffffffu, acc, 2);
        acc += __shfl_down_sync(0xffffffffu, acc, 1);
        if (s == 0 && valid) y[o] = b ? (acc + b[o]) : acc;
    }
}

// ---------------------------------------------------------------------------
// Persistent decoder: one block per batch element n, loops T=32 steps. All fp32.
// ---------------------------------------------------------------------------
__global__ __launch_bounds__(256)
void decoder_kernel(const float* __restrict__ cell_wh, const float* __restrict__ cell_bh,
                    const float* __restrict__ pointer_w, const float* __restrict__ pointer_b,
                    const float* __restrict__ query_w, const float* __restrict__ query_b,
                    const float* __restrict__ actor_w, const float* __restrict__ actor_b,
                    const float* __restrict__ critic_w, const float* __restrict__ critic_b,
                    const int* __restrict__ a_idx, const int* __restrict__ p_idx,
                    float* __restrict__ out)
{
    const int n = blockIdx.x;
    const int tid = threadIdx.x;

    __shared__ float sh_h[256];
    __shared__ float sh_gh[768];
    __shared__ float sh_q[256];
    __shared__ float sh_l[128];
    __shared__ float sh_zz[256];
    __shared__ float sh_pl[64];
    __shared__ float sh_al[16];
    __shared__ float sh_v[4];
    __shared__ float s_max, s_sum;

    sh_h[tid] = 0.f;
    __syncthreads();

    for (int t = 0; t < T_; t++) {
        __syncthreads();
        matvec8(sh_gh, cell_wh, cell_bh, sh_h, 768, 256);
        __syncthreads();

        const float* gi = g_GI + (size_t)(t * 64 + n) * 768;
        float h_old = sh_h[tid];
        float rg = 1.f / (1.f + __expf(-(gi[tid]       + sh_gh[tid])));
        float zg = 1.f / (1.f + __expf(-(gi[256 + tid] + sh_gh[256 + tid])));
        float tn;
        asm("tanh.approx.f32 %0, %1;" : "=f"(tn) : "f"(gi[512 + tid] + rg * sh_gh[512 + tid]));
        float hnew = (1.f - zg) * tn + zg * h_old;
        __syncthreads();
        sh_h[tid] = hnew;
        __syncthreads();

        matvec8(sh_pl, pointer_w, pointer_b, sh_h, 64, 256);
        matvec8(sh_q,  query_w,   query_b,   sh_h, 256, 256);
        matvec8(sh_v,  critic_w,  critic_b,  sh_h, 1, 256);
        __syncthreads();

        if (tid < 32) {
            float m = fmaxf(sh_pl[tid], sh_pl[tid + 32]);
#pragma unroll
            for (int o = 16; o > 0; o >>= 1) m = fmaxf(m, __shfl_xor_sync(0xffffffffu, m, o));
            if (tid == 0) s_max = m;
        }
        __syncthreads();
        if (tid < 64) sh_pl[tid] = __expf(sh_pl[tid] - s_max);
        __syncthreads();
        if (tid < 32) {
            float s = sh_pl[tid] + sh_pl[tid + 32];
#pragma unroll
            for (int o = 16; o > 0; o >>= 1) s += __shfl_xor_sync(0xffffffffu, s, o);
            if (tid == 0) s_sum = s;
        }

        const float* Kc = g_K + (size_t)(t * 64 + n) * (2 * 64 * 256);   // [128][256]
        __syncthreads();
        matvec8(sh_l, Kc, nullptr, sh_q, 128, 256);
        __syncthreads();

        {
            float acc = 0.f;
#pragma unroll 8
            for (int k2 = 0; k2 < 128; k2++) acc += sh_l[k2] * Kc[(size_t)k2 * 256 + tid];
            sh_zz[tid] = acc;
        }
        __syncthreads();

        matvec8(sh_al, actor_w, actor_b, sh_zz, 16, 256);
        __syncthreads();
        if (tid < 32) {
            float v = (tid < 16) ? sh_al[tid] : -1e30f;
            float m = v;
#pragma unroll
            for (int o = 16; o > 0; o >>= 1) m = fmaxf(m, __shfl_xor_sync(0xffffffffu, m, o));
            float e = (tid < 16) ? __expf(v - m) : 0.f;
            float s = e;
#pragma unroll
            for (int o = 16; o > 0; o >>= 1) s += __shfl_xor_sync(0xffffffffu, s, o);
            if (tid < 16) sh_al[tid] = e / s;
        }
        __syncthreads();

        float* orow = out + ((size_t)(t * 64 + n)) * 339;
        if (tid == 0) {
            orow[0] = (float)a_idx[t * 64 + n];
            orow[1] = (float)p_idx[t * 64 + n];
            orow[2] = sh_v[0];
        }
        orow[3 + tid] = sh_h[tid];
        if (tid < 16) orow[259 + tid] = sh_al[tid];
        if (tid < 64) orow[275 + tid] = sh_pl[tid] / s_sum;
    }
}

// ---------------------------------------------------------------------------
// Launch
// ---------------------------------------------------------------------------
extern "C" void kernel_launch(void* const* d_in, const int* in_sizes, int n_in,
                              void* d_out, int out_size)
{
    const float* condition = (const float*)d_in[0];
    const int*   lines     = (const int*)  d_in[1];
    const int*   a_idx     = (const int*)  d_in[2];
    const int*   p_idx     = (const int*)  d_in[3];
    const float* embed     = (const float*)d_in[4];
    const float* aemb      = (const float*)d_in[5];
    const float* gru_wi_f  = (const float*)d_in[6];
    const float* gru_wh_f  = (const float*)d_in[7];
    const float* gru_bi_f  = (const float*)d_in[8];
    const float* gru_bh_f  = (const float*)d_in[9];
    const float* gru_wi_b  = (const float*)d_in[10];
    const float* gru_wh_b  = (const float*)d_in[11];
    const float* gru_bi_b  = (const float*)d_in[12];
    const float* gru_bh_b  = (const float*)d_in[13];
    const float* f_w1      = (const float*)d_in[14];
    const float* f_b1      = (const float*)d_in[15];
    const float* f_w2      = (const float*)d_in[16];
    const float* f_b2      = (const float*)d_in[17];
    const float* cell_wi   = (const float*)d_in[18];
    const float* cell_wh   = (const float*)d_in[19];
    const float* cell_bi   = (const float*)d_in[20];
    const float* cell_bh   = (const float*)d_in[21];
    const float* critic_w  = (const float*)d_in[22];
    const float* critic_b  = (const float*)d_in[23];
    const float* pointer_w = (const float*)d_in[24];
    const float* pointer_b = (const float*)d_in[25];
    const float* actor_w   = (const float*)d_in[26];
    const float* actor_b   = (const float*)d_in[27];
    const float* query_w   = (const float*)d_in[28];
    const float* query_b   = (const float*)d_in[29];
    float* out = (float*)d_out;

    void *pXI_, *pXF1_, *pXF2_, *pGI_;
    cudaGetSymbolAddress(&pXI_,  g_XI);
    cudaGetSymbolAddress(&pXF1_, g_XF1);
    cudaGetSymbolAddress(&pXF2_, g_XF2);
    cudaGetSymbolAddress(&pGI_,  g_GI);
    float* pXI  = (float*)pXI_;
    float* pXF1 = (float*)pXF1_;
    float* pXF2 = (float*)pXF2_;
    float* pGI  = (float*)pGI_;

    // recurrence dynamic smem: h16 + sbh + sXI + rrs
    const int SMEM_REC = 32 * STRH * 2 + 768 * 4 + 32 * STRX * 4 + 32 * 4;
    cudaFuncSetAttribute(recur_kernel, cudaFuncAttributeMaxDynamicSharedMemorySize, SMEM_REC);

    // 0) permute Wh into fp16 B-fragments
    permute_wh16<<<192, 256>>>(gru_wh_f, gru_wh_b);

    // 1) input projections XI (fp32) for both GRU directions
    gemm_k<<<dim3(128, 6), 256>>>(0, nullptr, gru_wi_f, gru_bi_f, pXI,
                                  768, 256, 0, lines, embed, nullptr, nullptr, nullptr);
    gemm_k<<<dim3(128, 6), 256>>>(0, nullptr, gru_wi_b, gru_bi_b, pXI + 4096ull * 768,
                                  768, 256, 0, lines, embed, nullptr, nullptr, nullptr);

    // 2) decoder MLP + cell input gates (fp32)
    gemm_k<<<dim3(64, 2), 256>>>(1, nullptr, f_w1, f_b1, pXF1,
                                 256, 320, 1, nullptr, nullptr, condition, aemb, a_idx);
    gemm_k<<<dim3(64, 2), 256>>>(2, pXF1, f_w2, f_b2, pXF2,
                                 256, 256, 1, nullptr, nullptr, nullptr, nullptr, nullptr);
    gemm_k<<<dim3(64, 6), 256>>>(2, pXF2, cell_wi, cell_bi, pGI,
                                 768, 256, 0, nullptr, nullptr, nullptr, nullptr, nullptr);

    // 3) persistent fp16-MMA recurrence (128 blocks x 512 threads)
    recur_kernel<<<128, 512, SMEM_REC>>>(p_idx, gru_bh_f, gru_bh_b);

    // 4) persistent decoder (fp32)
    decoder_kernel<<<64, 256>>>(cell_wh, cell_bh, pointer_w, pointer_b,
                                query_w, query_b, actor_w, actor_b,
                                critic_w, critic_b, a_idx, p_idx, out);
}